// round 12
// baseline (speedup 1.0000x reference)
#include <cuda_runtime.h>

#define N_NODES  50000
#define N_EDGES  800000
#define N_GRAPHS 64
#define NEG      0.2f

// ---------------- device scratch (no allocations allowed) ----------------
__device__ float4 g_x4[N_NODES];                      // (s1, x0, x1, x2)
__device__ float  g_d1[N_NODES];                      // d1 per node (compact)
__device__ float4 g_agg1[N_NODES];                    // (sum, ax, ay, az)
__device__ __align__(16) float g_h[N_NODES * 16];     // [s2,h0,h1,h2 | h3..h6 | h7,-,-,- | ----] 64B/node
__device__ float  g_dd2[N_NODES];                     // d2 per node (compact, dst-gathered)
__device__ __align__(16) float g_agg2[N_NODES * 16];  // [sum,a0,a1,a2 | a3..a6 | a7,...] 64B/node
__device__ float  g_wa2[16];                          // wa_src2[8], wa_dst2[8]

__device__ __forceinline__ float lrelu(float v) { return v > 0.f ? v : NEG * v; }

__device__ __forceinline__ void red_add_v4(float* addr, float a, float b, float c, float d) {
    asm volatile("red.global.add.v4.f32 [%0], {%1,%2,%3,%4};"
                 :: "l"(addr), "f"(a), "f"(b), "f"(c), "f"(d) : "memory");
}
__device__ __forceinline__ void red_add_f32(float* addr, float a) {
    asm volatile("red.global.add.f32 [%0], %1;"
                 :: "l"(addr), "f"(a) : "memory");
}

// -------- fused prep + layer1 node init (every block folds wa1 locally) --------
__global__ void __launch_bounds__(128) k_init(const float* __restrict__ x,
                      const float* __restrict__ W1, const float* __restrict__ as1,
                      const float* __restrict__ ad1,
                      const float* __restrict__ W2, const float* __restrict__ as2,
                      const float* __restrict__ ad2,
                      float* __restrict__ out) {
    __shared__ float swa[6];     // wa_src1[3], wa_dst1[3]
    int tid = threadIdx.x;
    if (tid < 6) {
        int c = tid % 3;
        const float* av = (tid < 3) ? as1 : ad1;
        float a = 0.f;
        #pragma unroll
        for (int j = 0; j < 8; j++) a += W1[c * 8 + j] * av[j];
        swa[tid] = a;
    }
    // block 0 extra duty: fold wa2 and zero the output
    if (blockIdx.x == 0) {
        if (tid < N_GRAPHS) out[tid] = 0.f;
        int w = tid >> 5, lane = tid & 31;
        #pragma unroll
        for (int kk = 0; kk < 2; kk++) {
            int k = w * 2 + kk;             // 4 warps x 2 = 8 rows
            float a = 0.f, b = 0.f;
            #pragma unroll
            for (int j = 0; j < 8; j++) {
                int f = lane * 8 + j;
                float wv = W2[k * 256 + f];
                a += wv * as2[f];
                b += wv * ad2[f];
            }
            #pragma unroll
            for (int o = 16; o > 0; o >>= 1) {
                a += __shfl_down_sync(0xffffffffu, a, o);
                b += __shfl_down_sync(0xffffffffu, b, o);
            }
            if (lane == 0) { g_wa2[k] = a; g_wa2[8 + k] = b; }
        }
    }
    __syncthreads();

    int v = blockIdx.x * 128 + tid;
    if (v >= N_NODES) return;
    float x0 = x[v * 3 + 0], x1 = x[v * 3 + 1], x2 = x[v * 3 + 2];
    float s = x0 * swa[0] + x1 * swa[1] + x2 * swa[2];
    float d = x0 * swa[3] + x1 * swa[4] + x2 * swa[5];
    g_x4[v] = make_float4(s, x0, x1, x2);
    g_d1[v] = d;
    g_agg1[v] = make_float4(0.f, 0.f, 0.f, 0.f);
}

// ---------------- layer1 edge pass: exp(logit) + v4 scatter --------------------
__global__ void __launch_bounds__(256) k_edgeB1(const int* __restrict__ ei) {
    int i = blockIdx.x * blockDim.x + threadIdx.x;
    if (i >= N_EDGES) return;
    int s = ei[i], d = ei[N_EDGES + i];
    float4 f = g_x4[s];
    float w = __expf(lrelu(f.x + g_d1[d]));
    red_add_v4((float*)&g_agg1[d], w, w * f.y, w * f.z, w * f.w);
}

// ------- layer1 finalize: self-loop, normalize, project W1, prep layer2 --------
__global__ void __launch_bounds__(128) k_node1_fin(const float* __restrict__ W1,
                                                   const float* __restrict__ b1) {
    int v = blockIdx.x * 128 + threadIdx.x;
    if (v >= N_NODES) return;
    float4 f = g_x4[v];
    float w = __expf(lrelu(f.x + g_d1[v]));       // self-loop weight
    float4 a = g_agg1[v];
    float inv = 1.f / (a.x + w);
    float t0 = (a.y + w * f.y) * inv;
    float t1 = (a.z + w * f.z) * inv;
    float t2 = (a.w + w * f.w) * inv;

    float y[8];
    float s2 = 0.f, d2 = 0.f;
    #pragma unroll
    for (int k = 0; k < 8; k++) {
        float t = t0 * W1[k] + t1 * W1[8 + k] + t2 * W1[16 + k] + b1[k];
        t = t > 0.f ? t : 0.f;                    // relu
        y[k] = t;
        s2 += t * g_wa2[k];
        d2 += t * g_wa2[8 + k];
    }
    float4* hv = (float4*)(g_h + v * 16);
    hv[0] = make_float4(s2, y[0], y[1], y[2]);
    hv[1] = make_float4(y[3], y[4], y[5], y[6]);
    hv[2] = make_float4(y[7], 0.f, 0.f, 0.f);
    g_dd2[v] = d2;
    float4* ag = (float4*)(g_agg2 + v * 16);
    ag[0] = make_float4(0.f, 0.f, 0.f, 0.f);
    ag[1] = make_float4(0.f, 0.f, 0.f, 0.f);
    ag[2] = make_float4(0.f, 0.f, 0.f, 0.f);
}

// ---------------- layer2 edge pass: exp + 2x v4 + scalar red -------------------
__global__ void __launch_bounds__(256) k_edgeB2(const int* __restrict__ ei) {
    int i = blockIdx.x * blockDim.x + threadIdx.x;
    if (i >= N_EDGES) return;
    int s = ei[i], d = ei[N_EDGES + i];
    const float4* hp = (const float4*)(g_h + s * 16);
    float4 A = hp[0];                       // s2, h0, h1, h2
    float4 B = hp[1];                       // h3..h6
    float  h7 = g_h[s * 16 + 8];
    float  d2 = g_dd2[d];                   // compact dst gather
    float w = __expf(lrelu(A.x + d2));
    float* ag = g_agg2 + d * 16;
    red_add_v4(ag,     w,       w * A.y, w * A.z, w * A.w);   // sum, a0, a1, a2
    red_add_v4(ag + 4, w * B.x, w * B.y, w * B.z, w * B.w);   // a3..a6
    red_add_f32(ag + 8, w * h7);                              // a7
}

// -------- layer2 finalize + W2 projection + ReLU + FC + graph pooling ----------
__global__ void __launch_bounds__(128) k_node2_fin(const int* __restrict__ batch,
                            const float* __restrict__ W2,
                            const float* __restrict__ b2,
                            const float* __restrict__ fcw,
                            const float* __restrict__ fcb,
                            float* __restrict__ out) {
    __shared__ float4 sW2[512];   // [k][f/4] : k*64 + f4
    __shared__ float4 sb2[64];
    __shared__ float4 sfw[64];
    __shared__ float  sg[N_GRAPHS];

    int tid = threadIdx.x;
    for (int j = tid; j < 512; j += 128)
        sW2[j] = ((const float4*)W2)[j];
    for (int j = tid; j < 64; j += 128) {
        sb2[j] = ((const float4*)b2)[j];
        sfw[j] = ((const float4*)fcw)[j];
    }
    if (tid < N_GRAPHS) sg[tid] = 0.f;
    __syncthreads();

    int v = blockIdx.x * 128 + tid;
    if (v < N_NODES) {
        const float4* hp = (const float4*)(g_h + v * 16);
        float4 A = hp[0];                         // s2, h0, h1, h2
        float4 B = hp[1];                         // h3..h6
        float  h7 = g_h[v * 16 + 8];
        float  d2 = g_dd2[v];
        float w = __expf(lrelu(A.x + d2));        // self-loop weight
        const float* ag = g_agg2 + v * 16;
        float inv = 1.f / (ag[0] + w);
        float t[8];
        t[0] = (ag[1] + w * A.y) * inv;
        t[1] = (ag[2] + w * A.z) * inv;
        t[2] = (ag[3] + w * A.w) * inv;
        t[3] = (ag[4] + w * B.x) * inv;
        t[4] = (ag[5] + w * B.y) * inv;
        t[5] = (ag[6] + w * B.z) * inv;
        t[6] = (ag[7] + w * B.w) * inv;
        t[7] = (ag[8] + w * h7) * inv;

        float acc = 0.f;
        #pragma unroll 4
        for (int f4 = 0; f4 < 64; f4++) {
            float4 y = sb2[f4];
            #pragma unroll
            for (int k = 0; k < 8; k++) {
                float4 wv = sW2[k * 64 + f4];
                y.x += t[k] * wv.x;
                y.y += t[k] * wv.y;
                y.z += t[k] * wv.z;
                y.w += t[k] * wv.w;
            }
            y.x = y.x > 0.f ? y.x : 0.f;
            y.y = y.y > 0.f ? y.y : 0.f;
            y.z = y.z > 0.f ? y.z : 0.f;
            y.w = y.w > 0.f ? y.w : 0.f;
            float4 fw = sfw[f4];
            acc += y.x * fw.x + y.y * fw.y + y.z * fw.z + y.w * fw.w;
        }
        acc += fcb[0];
        atomicAdd(&sg[batch[v]], acc);
    }
    __syncthreads();
    if (tid < N_GRAPHS) atomicAdd(&out[tid], sg[tid]);
}

// --------------------------------- launch --------------------------------------
extern "C" void kernel_launch(void* const* d_in, const int* in_sizes, int n_in,
                              void* d_out, int out_size) {
    const float* x     = (const float*)d_in[0];
    const int*   ei    = (const int*)d_in[1];     // int64 delivered as int32
    // d_in[2] = edge_attr (unused)
    const int*   batch = (const int*)d_in[3];
    const float* W1    = (const float*)d_in[4];
    const float* as1   = (const float*)d_in[5];
    const float* ad1   = (const float*)d_in[6];
    const float* b1    = (const float*)d_in[7];
    const float* W2    = (const float*)d_in[8];
    const float* as2   = (const float*)d_in[9];
    const float* ad2   = (const float*)d_in[10];
    const float* b2    = (const float*)d_in[11];
    const float* fcw   = (const float*)d_in[12];
    const float* fcb   = (const float*)d_in[13];
    float*       out   = (float*)d_out;

    const int EB = (N_EDGES + 255) / 256;   // 3125
    const int NB = (N_NODES + 127) / 128;   // 391

    k_init<<<NB, 128>>>(x, W1, as1, ad1, W2, as2, ad2, out);
    k_edgeB1<<<EB, 256>>>(ei);
    k_node1_fin<<<NB, 128>>>(W1, b1);
    k_edgeB2<<<EB, 256>>>(ei);
    k_node2_fin<<<NB, 128>>>(batch, W2, b2, fcw, fcb, out);
}

// round 13
// speedup vs baseline: 1.0566x; 1.0566x over previous
#include <cuda_runtime.h>
#include <cuda_fp16.h>

#define N_NODES  50000
#define N_EDGES  800000
#define N_GRAPHS 64
#define NEG      0.2f

// ---------------- device scratch (no allocations allowed) ----------------
__device__ float4 g_x4[N_NODES];                      // (s1, x0, x1, x2)
__device__ float  g_d1[N_NODES];                      // d1 per node (compact)
__device__ float4 g_agg1[N_NODES];                    // (sum, ax, ay, az)
__device__ __align__(32) float g_h[N_NODES * 8];      // [s2_f32, h01_f16x2, h23, h45, h67, pad3] 32B/node
__device__ float  g_dd2[N_NODES];                     // d2 per node (compact, dst-gathered)
__device__ __align__(16) float g_agg2[N_NODES * 16];  // [sum,a0,a1,a2 | a3..a6 | a7,...] 64B/node
__device__ float  g_wa2[16];                          // wa_src2[8], wa_dst2[8]

__device__ __forceinline__ float lrelu(float v) { return v > 0.f ? v : NEG * v; }

__device__ __forceinline__ void red_add_v4(float* addr, float a, float b, float c, float d) {
    asm volatile("red.global.add.v4.f32 [%0], {%1,%2,%3,%4};"
                 :: "l"(addr), "f"(a), "f"(b), "f"(c), "f"(d) : "memory");
}
__device__ __forceinline__ void red_add_f32(float* addr, float a) {
    asm volatile("red.global.add.f32 [%0], %1;"
                 :: "l"(addr), "f"(a) : "memory");
}

__device__ __forceinline__ float pack_h2(float a, float b) {
    __half2 p = __floats2half2_rn(a, b);
    return *reinterpret_cast<float*>(&p);
}
__device__ __forceinline__ float2 unpack_h2(float v) {
    __half2 p = *reinterpret_cast<__half2*>(&v);
    return __half22float2(p);
}

// -------- fused prep + layer1 node init (every block folds wa1 locally) --------
__global__ void __launch_bounds__(128) k_init(const float* __restrict__ x,
                      const float* __restrict__ W1, const float* __restrict__ as1,
                      const float* __restrict__ ad1,
                      const float* __restrict__ W2, const float* __restrict__ as2,
                      const float* __restrict__ ad2,
                      float* __restrict__ out) {
    __shared__ float swa[6];     // wa_src1[3], wa_dst1[3]
    int tid = threadIdx.x;
    if (tid < 6) {
        int c = tid % 3;
        const float* av = (tid < 3) ? as1 : ad1;
        float a = 0.f;
        #pragma unroll
        for (int j = 0; j < 8; j++) a += W1[c * 8 + j] * av[j];
        swa[tid] = a;
    }
    // block 0 extra duty: fold wa2 and zero the output
    if (blockIdx.x == 0) {
        if (tid < N_GRAPHS) out[tid] = 0.f;
        int w = tid >> 5, lane = tid & 31;
        #pragma unroll
        for (int kk = 0; kk < 2; kk++) {
            int k = w * 2 + kk;             // 4 warps x 2 = 8 rows
            float a = 0.f, b = 0.f;
            #pragma unroll
            for (int j = 0; j < 8; j++) {
                int f = lane * 8 + j;
                float wv = W2[k * 256 + f];
                a += wv * as2[f];
                b += wv * ad2[f];
            }
            #pragma unroll
            for (int o = 16; o > 0; o >>= 1) {
                a += __shfl_down_sync(0xffffffffu, a, o);
                b += __shfl_down_sync(0xffffffffu, b, o);
            }
            if (lane == 0) { g_wa2[k] = a; g_wa2[8 + k] = b; }
        }
    }
    __syncthreads();

    int v = blockIdx.x * 128 + tid;
    if (v >= N_NODES) return;
    float x0 = x[v * 3 + 0], x1 = x[v * 3 + 1], x2 = x[v * 3 + 2];
    float s = x0 * swa[0] + x1 * swa[1] + x2 * swa[2];
    float d = x0 * swa[3] + x1 * swa[4] + x2 * swa[5];
    g_x4[v] = make_float4(s, x0, x1, x2);
    g_d1[v] = d;
    g_agg1[v] = make_float4(0.f, 0.f, 0.f, 0.f);
}

// ---------------- layer1 edge pass: exp(logit) + v4 scatter --------------------
__global__ void __launch_bounds__(256) k_edgeB1(const int* __restrict__ ei) {
    int i = blockIdx.x * blockDim.x + threadIdx.x;
    if (i >= N_EDGES) return;
    int s = ei[i], d = ei[N_EDGES + i];
    float4 f = g_x4[s];
    float w = __expf(lrelu(f.x + g_d1[d]));
    red_add_v4((float*)&g_agg1[d], w, w * f.y, w * f.z, w * f.w);
}

// ------- layer1 finalize: self-loop, normalize, project W1, prep layer2 --------
__global__ void __launch_bounds__(128) k_node1_fin(const float* __restrict__ W1,
                                                   const float* __restrict__ b1) {
    int v = blockIdx.x * 128 + threadIdx.x;
    if (v >= N_NODES) return;
    float4 f = g_x4[v];
    float w = __expf(lrelu(f.x + g_d1[v]));       // self-loop weight
    float4 a = g_agg1[v];
    float inv = 1.f / (a.x + w);
    float t0 = (a.y + w * f.y) * inv;
    float t1 = (a.z + w * f.z) * inv;
    float t2 = (a.w + w * f.w) * inv;

    float y[8];
    float s2 = 0.f, d2 = 0.f;
    #pragma unroll
    for (int k = 0; k < 8; k++) {
        float t = t0 * W1[k] + t1 * W1[8 + k] + t2 * W1[16 + k] + b1[k];
        t = t > 0.f ? t : 0.f;                    // relu
        y[k] = t;
        s2 += t * g_wa2[k];
        d2 += t * g_wa2[8 + k];
    }
    // pack h as fp16 pairs: [s2, h01, h23, h45] + [h67]
    float4* hv = (float4*)(g_h + v * 8);
    hv[0] = make_float4(s2, pack_h2(y[0], y[1]), pack_h2(y[2], y[3]), pack_h2(y[4], y[5]));
    g_h[v * 8 + 4] = pack_h2(y[6], y[7]);
    g_dd2[v] = d2;
    float4* ag = (float4*)(g_agg2 + v * 16);
    ag[0] = make_float4(0.f, 0.f, 0.f, 0.f);
    ag[1] = make_float4(0.f, 0.f, 0.f, 0.f);
    ag[2] = make_float4(0.f, 0.f, 0.f, 0.f);
}

// ---------------- layer2 edge pass: exp + 2x v4 + scalar red -------------------
__global__ void __launch_bounds__(256) k_edgeB2(const int* __restrict__ ei) {
    int i = blockIdx.x * blockDim.x + threadIdx.x;
    if (i >= N_EDGES) return;
    int s = ei[i], d = ei[N_EDGES + i];
    const float4 f = *(const float4*)(g_h + s * 8);   // s2, h01, h23, h45
    float h67raw = g_h[s * 8 + 4];
    float d2 = g_dd2[d];                              // compact dst gather
    float w = __expf(lrelu(f.x + d2));
    float2 h01 = unpack_h2(f.y);
    float2 h23 = unpack_h2(f.z);
    float2 h45 = unpack_h2(f.w);
    float2 h67 = unpack_h2(h67raw);
    float* ag = g_agg2 + d * 16;
    red_add_v4(ag,     w,         w * h01.x, w * h01.y, w * h23.x);  // sum, a0, a1, a2
    red_add_v4(ag + 4, w * h23.y, w * h45.x, w * h45.y, w * h67.x);  // a3..a6
    red_add_f32(ag + 8, w * h67.y);                                  // a7
}

// -------- layer2 finalize + W2 projection + ReLU + FC + graph pooling ----------
__global__ void __launch_bounds__(128) k_node2_fin(const int* __restrict__ batch,
                            const float* __restrict__ W2,
                            const float* __restrict__ b2,
                            const float* __restrict__ fcw,
                            const float* __restrict__ fcb,
                            float* __restrict__ out) {
    __shared__ float4 sW2[512];   // [k][f/4] : k*64 + f4
    __shared__ float4 sb2[64];
    __shared__ float4 sfw[64];
    __shared__ float  sg[N_GRAPHS];

    int tid = threadIdx.x;
    for (int j = tid; j < 512; j += 128)
        sW2[j] = ((const float4*)W2)[j];
    for (int j = tid; j < 64; j += 128) {
        sb2[j] = ((const float4*)b2)[j];
        sfw[j] = ((const float4*)fcw)[j];
    }
    if (tid < N_GRAPHS) sg[tid] = 0.f;
    __syncthreads();

    int v = blockIdx.x * 128 + tid;
    if (v < N_NODES) {
        const float4 f = *(const float4*)(g_h + v * 8);
        float h67raw = g_h[v * 8 + 4];
        float d2 = g_dd2[v];
        float w = __expf(lrelu(f.x + d2));        // self-loop weight
        float2 h01 = unpack_h2(f.y);
        float2 h23 = unpack_h2(f.z);
        float2 h45 = unpack_h2(f.w);
        float2 h67 = unpack_h2(h67raw);
        const float* ag = g_agg2 + v * 16;
        float inv = 1.f / (ag[0] + w);
        float t[8];
        t[0] = (ag[1] + w * h01.x) * inv;
        t[1] = (ag[2] + w * h01.y) * inv;
        t[2] = (ag[3] + w * h23.x) * inv;
        t[3] = (ag[4] + w * h23.y) * inv;
        t[4] = (ag[5] + w * h45.x) * inv;
        t[5] = (ag[6] + w * h45.y) * inv;
        t[6] = (ag[7] + w * h67.x) * inv;
        t[7] = (ag[8] + w * h67.y) * inv;

        float acc = 0.f;
        #pragma unroll 4
        for (int f4 = 0; f4 < 64; f4++) {
            float4 y = sb2[f4];
            #pragma unroll
            for (int k = 0; k < 8; k++) {
                float4 wv = sW2[k * 64 + f4];
                y.x += t[k] * wv.x;
                y.y += t[k] * wv.y;
                y.z += t[k] * wv.z;
                y.w += t[k] * wv.w;
            }
            y.x = y.x > 0.f ? y.x : 0.f;
            y.y = y.y > 0.f ? y.y : 0.f;
            y.z = y.z > 0.f ? y.z : 0.f;
            y.w = y.w > 0.f ? y.w : 0.f;
            float4 fw = sfw[f4];
            acc += y.x * fw.x + y.y * fw.y + y.z * fw.z + y.w * fw.w;
        }
        acc += fcb[0];
        atomicAdd(&sg[batch[v]], acc);
    }
    __syncthreads();
    if (tid < N_GRAPHS) atomicAdd(&out[tid], sg[tid]);
}

// --------------------------------- launch --------------------------------------
extern "C" void kernel_launch(void* const* d_in, const int* in_sizes, int n_in,
                              void* d_out, int out_size) {
    const float* x     = (const float*)d_in[0];
    const int*   ei    = (const int*)d_in[1];     // int64 delivered as int32
    // d_in[2] = edge_attr (unused)
    const int*   batch = (const int*)d_in[3];
    const float* W1    = (const float*)d_in[4];
    const float* as1   = (const float*)d_in[5];
    const float* ad1   = (const float*)d_in[6];
    const float* b1    = (const float*)d_in[7];
    const float* W2    = (const float*)d_in[8];
    const float* as2   = (const float*)d_in[9];
    const float* ad2   = (const float*)d_in[10];
    const float* b2    = (const float*)d_in[11];
    const float* fcw   = (const float*)d_in[12];
    const float* fcb   = (const float*)d_in[13];
    float*       out   = (float*)d_out;

    const int EB = (N_EDGES + 255) / 256;   // 3125
    const int NB = (N_NODES + 127) / 128;   // 391

    k_init<<<NB, 128>>>(x, W1, as1, ad1, W2, as2, ad2, out);
    k_edgeB1<<<EB, 256>>>(ei);
    k_node1_fin<<<NB, 128>>>(W1, b1);
    k_edgeB2<<<EB, 256>>>(ei);
    k_node2_fin<<<NB, 128>>>(batch, W2, b2, fcw, fcb, out);
}

// round 16
// speedup vs baseline: 1.1379x; 1.0770x over previous
#include <cuda_runtime.h>
#include <cuda_fp16.h>

#define N_NODES  50000
#define N_EDGES  800000
#define N_GRAPHS 64
#define NEG      0.2f

// ---------------- device scratch (no allocations allowed) ----------------
__device__ float4 g_x4[N_NODES];                      // (s1, x0, x1, x2)
__device__ float  g_d1[N_NODES];                      // d1 per node (compact)
__device__ float4 g_agg1[N_NODES];                    // (sum, ax, ay, az)
__device__ __align__(32) float g_h[N_NODES * 8];      // [s2_f32, h01_f16x2, h23, h45, h67, pad3] 32B/node
__device__ float  g_dd2[N_NODES];                     // d2 per node (compact, dst-gathered)
__device__ __align__(32) float g_agg2[N_NODES * 8];   // [sum,a0,a1,a2 f32 | a34,a56,a7x f16x2 | pad] 32B/node
__device__ float  g_wa2[16];                          // wa_src2[8], wa_dst2[8]

__device__ __forceinline__ float lrelu(float v) { return v > 0.f ? v : NEG * v; }

__device__ __forceinline__ void red_add_v4(float* addr, float a, float b, float c, float d) {
    asm volatile("red.global.add.v4.f32 [%0], {%1,%2,%3,%4};"
                 :: "l"(addr), "f"(a), "f"(b), "f"(c), "f"(d) : "memory");
}
__device__ __forceinline__ void red_add_v4_f16x2(float* addr, unsigned a, unsigned b,
                                                 unsigned c, unsigned d) {
    asm volatile("red.global.add.noftz.v4.f16x2 [%0], {%1,%2,%3,%4};"
                 :: "l"(addr), "r"(a), "r"(b), "r"(c), "r"(d) : "memory");
}

__device__ __forceinline__ float pack_h2(float a, float b) {
    __half2 p = __floats2half2_rn(a, b);
    return *reinterpret_cast<float*>(&p);
}
__device__ __forceinline__ float2 unpack_h2(float v) {
    __half2 p = *reinterpret_cast<__half2*>(&v);
    return __half22float2(p);
}
__device__ __forceinline__ __half2 as_h2(float v) {
    return *reinterpret_cast<__half2*>(&v);
}
__device__ __forceinline__ unsigned as_u32(__half2 v) {
    return *reinterpret_cast<unsigned*>(&v);
}

// -------- fused prep + layer1 node init (every block folds wa1 locally) --------
__global__ void __launch_bounds__(128) k_init(const float* __restrict__ x,
                      const float* __restrict__ W1, const float* __restrict__ as1,
                      const float* __restrict__ ad1,
                      const float* __restrict__ W2, const float* __restrict__ as2,
                      const float* __restrict__ ad2,
                      float* __restrict__ out) {
    __shared__ float swa[6];     // wa_src1[3], wa_dst1[3]
    int tid = threadIdx.x;
    if (tid < 6) {
        int c = tid % 3;
        const float* av = (tid < 3) ? as1 : ad1;
        float a = 0.f;
        #pragma unroll
        for (int j = 0; j < 8; j++) a += W1[c * 8 + j] * av[j];
        swa[tid] = a;
    }
    // block 0 extra duty: fold wa2 and zero the output
    if (blockIdx.x == 0) {
        if (tid < N_GRAPHS) out[tid] = 0.f;
        int w = tid >> 5, lane = tid & 31;
        #pragma unroll
        for (int kk = 0; kk < 2; kk++) {
            int k = w * 2 + kk;             // 4 warps x 2 = 8 rows
            float a = 0.f, b = 0.f;
            #pragma unroll
            for (int j = 0; j < 8; j++) {
                int f = lane * 8 + j;
                float wv = W2[k * 256 + f];
                a += wv * as2[f];
                b += wv * ad2[f];
            }
            #pragma unroll
            for (int o = 16; o > 0; o >>= 1) {
                a += __shfl_down_sync(0xffffffffu, a, o);
                b += __shfl_down_sync(0xffffffffu, b, o);
            }
            if (lane == 0) { g_wa2[k] = a; g_wa2[8 + k] = b; }
        }
    }
    __syncthreads();

    int v = blockIdx.x * 128 + tid;
    if (v >= N_NODES) return;
    float x0 = x[v * 3 + 0], x1 = x[v * 3 + 1], x2 = x[v * 3 + 2];
    float s = x0 * swa[0] + x1 * swa[1] + x2 * swa[2];
    float d = x0 * swa[3] + x1 * swa[4] + x2 * swa[5];
    g_x4[v] = make_float4(s, x0, x1, x2);
    g_d1[v] = d;
    g_agg1[v] = make_float4(0.f, 0.f, 0.f, 0.f);
}

// ---------------- layer1 edge pass: exp(logit) + v4 scatter --------------------
__global__ void __launch_bounds__(256) k_edgeB1(const int* __restrict__ ei) {
    int i = blockIdx.x * blockDim.x + threadIdx.x;
    if (i >= N_EDGES) return;
    int s = ei[i], d = ei[N_EDGES + i];
    float4 f = g_x4[s];
    float w = __expf(lrelu(f.x + g_d1[d]));
    red_add_v4((float*)&g_agg1[d], w, w * f.y, w * f.z, w * f.w);
}

// ------- layer1 finalize: self-loop, normalize, project W1, prep layer2 --------
__global__ void __launch_bounds__(128) k_node1_fin(const float* __restrict__ W1,
                                                   const float* __restrict__ b1) {
    int v = blockIdx.x * 128 + threadIdx.x;
    if (v >= N_NODES) return;
    float4 f = g_x4[v];
    float w = __expf(lrelu(f.x + g_d1[v]));       // self-loop weight
    float4 a = g_agg1[v];
    float inv = 1.f / (a.x + w);
    float t0 = (a.y + w * f.y) * inv;
    float t1 = (a.z + w * f.z) * inv;
    float t2 = (a.w + w * f.w) * inv;

    float y[8];
    float s2 = 0.f, d2 = 0.f;
    #pragma unroll
    for (int k = 0; k < 8; k++) {
        float t = t0 * W1[k] + t1 * W1[8 + k] + t2 * W1[16 + k] + b1[k];
        t = t > 0.f ? t : 0.f;                    // relu
        y[k] = t;
        s2 += t * g_wa2[k];
        d2 += t * g_wa2[8 + k];
    }
    // pack h as fp16 pairs: [s2, h01, h23, h45] + [h67]
    float4* hv = (float4*)(g_h + v * 8);
    hv[0] = make_float4(s2, pack_h2(y[0], y[1]), pack_h2(y[2], y[3]), pack_h2(y[4], y[5]));
    g_h[v * 8 + 4] = pack_h2(y[6], y[7]);
    g_dd2[v] = d2;
    // zero accumulator record (32B)
    float4* ag = (float4*)(g_agg2 + v * 8);
    ag[0] = make_float4(0.f, 0.f, 0.f, 0.f);
    ag[1] = make_float4(0.f, 0.f, 0.f, 0.f);
}

// -------- layer2 edge pass: exp + v4.f32 red + v4.f16x2 red (2 requests) -------
__global__ void __launch_bounds__(256) k_edgeB2(const int* __restrict__ ei) {
    int i = blockIdx.x * blockDim.x + threadIdx.x;
    if (i >= N_EDGES) return;
    int s = ei[i], d = ei[N_EDGES + i];
    const float4 f = *(const float4*)(g_h + s * 8);   // s2, h01, h23, h45
    float h67raw = g_h[s * 8 + 4];                    // same 32B sector as f (L1 hit)
    float d2 = g_dd2[d];                              // compact dst gather
    float w = __expf(lrelu(f.x + d2));
    float2 h01 = unpack_h2(f.y);
    float2 h23 = unpack_h2(f.z);
    // fp16 lanes for a3..a7
    __half2 h23h = as_h2(f.z);
    __half2 h45h = as_h2(f.w);
    __half2 h67h = as_h2(h67raw);
    __half2 p34 = __halves2half2(__high2half(h23h), __low2half(h45h));  // (h3,h4)
    __half2 p56 = __halves2half2(__high2half(h45h), __low2half(h67h));  // (h5,h6)
    __half2 p7z = __halves2half2(__high2half(h67h), __float2half(0.f)); // (h7,0)
    __half2 wh = __float2half2_rn(w);
    float* ag = g_agg2 + d * 8;
    red_add_v4(ag, w, w * h01.x, w * h01.y, w * h23.x);                 // sum, a0, a1, a2
    red_add_v4_f16x2(ag + 4, as_u32(__hmul2(wh, p34)),
                             as_u32(__hmul2(wh, p56)),
                             as_u32(__hmul2(wh, p7z)), 0u);             // a3..a7 (fp16)
}

// -------- layer2 finalize + W2 projection + ReLU + FC + graph pooling ----------
__global__ void __launch_bounds__(128) k_node2_fin(const int* __restrict__ batch,
                            const float* __restrict__ W2,
                            const float* __restrict__ b2,
                            const float* __restrict__ fcw,
                            const float* __restrict__ fcb,
                            float* __restrict__ out) {
    __shared__ float4 sW2[512];   // [k][f/4] : k*64 + f4
    __shared__ float4 sb2[64];
    __shared__ float4 sfw[64];
    __shared__ float  sg[N_GRAPHS];

    int tid = threadIdx.x;
    for (int j = tid; j < 512; j += 128)
        sW2[j] = ((const float4*)W2)[j];
    for (int j = tid; j < 64; j += 128) {
        sb2[j] = ((const float4*)b2)[j];
        sfw[j] = ((const float4*)fcw)[j];
    }
    if (tid < N_GRAPHS) sg[tid] = 0.f;
    __syncthreads();

    int v = blockIdx.x * 128 + tid;
    if (v < N_NODES) {
        const float4 f = *(const float4*)(g_h + v * 8);
        float h67raw = g_h[v * 8 + 4];
        float d2 = g_dd2[v];
        float w = __expf(lrelu(f.x + d2));        // self-loop weight
        float2 h01 = unpack_h2(f.y);
        float2 h23 = unpack_h2(f.z);
        float2 h45 = unpack_h2(f.w);
        float2 h67 = unpack_h2(h67raw);
        const float* ag = g_agg2 + v * 8;
        float2 a34 = unpack_h2(ag[4]);
        float2 a56 = unpack_h2(ag[5]);
        float2 a7x = unpack_h2(ag[6]);
        float inv = 1.f / (ag[0] + w);
        float t[8];
        t[0] = (ag[1]  + w * h01.x) * inv;
        t[1] = (ag[2]  + w * h01.y) * inv;
        t[2] = (ag[3]  + w * h23.x) * inv;
        t[3] = (a34.x + w * h23.y) * inv;
        t[4] = (a34.y + w * h45.x) * inv;
        t[5] = (a56.x + w * h45.y) * inv;
        t[6] = (a56.y + w * h67.x) * inv;
        t[7] = (a7x.x + w * h67.y) * inv;

        float acc = 0.f;
        #pragma unroll 4
        for (int f4 = 0; f4 < 64; f4++) {
            float4 y = sb2[f4];
            #pragma unroll
            for (int k = 0; k < 8; k++) {
                float4 wv = sW2[k * 64 + f4];
                y.x += t[k] * wv.x;
                y.y += t[k] * wv.y;
                y.z += t[k] * wv.z;
                y.w += t[k] * wv.w;
            }
            y.x = y.x > 0.f ? y.x : 0.f;
            y.y = y.y > 0.f ? y.y : 0.f;
            y.z = y.z > 0.f ? y.z : 0.f;
            y.w = y.w > 0.f ? y.w : 0.f;
            float4 fw = sfw[f4];
            acc += y.x * fw.x + y.y * fw.y + y.z * fw.z + y.w * fw.w;
        }
        acc += fcb[0];
        atomicAdd(&sg[batch[v]], acc);
    }
    __syncthreads();
    if (tid < N_GRAPHS) atomicAdd(&out[tid], sg[tid]);
}

// --------------------------------- launch --------------------------------------
extern "C" void kernel_launch(void* const* d_in, const int* in_sizes, int n_in,
                              void* d_out, int out_size) {
    const float* x     = (const float*)d_in[0];
    const int*   ei    = (const int*)d_in[1];     // int64 delivered as int32
    // d_in[2] = edge_attr (unused)
    const int*   batch = (const int*)d_in[3];
    const float* W1    = (const float*)d_in[4];
    const float* as1   = (const float*)d_in[5];
    const float* ad1   = (const float*)d_in[6];
    const float* b1    = (const float*)d_in[7];
    const float* W2    = (const float*)d_in[8];
    const float* as2   = (const float*)d_in[9];
    const float* ad2   = (const float*)d_in[10];
    const float* b2    = (const float*)d_in[11];
    const float* fcw   = (const float*)d_in[12];
    const float* fcb   = (const float*)d_in[13];
    float*       out   = (float*)d_out;

    const int EB = (N_EDGES + 255) / 256;   // 3125
    const int NB = (N_NODES + 127) / 128;   // 391

    k_init<<<NB, 128>>>(x, W1, as1, ad1, W2, as2, ad2, out);
    k_edgeB1<<<EB, 256>>>(ei);
    k_node1_fin<<<NB, 128>>>(W1, b1);
    k_edgeB2<<<EB, 256>>>(ei);
    k_node2_fin<<<NB, 128>>>(batch, W2, b2, fcw, fcb, out);
}